// round 6
// baseline (speedup 1.0000x reference)
#include <cuda_runtime.h>
#include <cuda_fp16.h>
#include <cstdint>

// ---------------------------------------------------------------------------
// LeWinAttention round 6: GEMMs on fp16 mma.sync m16n8k16 (fp32 accum).
// CTA tile 128x64, BK=32, 2-stage smem double buffer, pad-40 half layout.
// tcgen05 unavailable (harness targets sm_103 without 'a').
// ---------------------------------------------------------------------------

__device__ float g_qkv[402653184];   // 8192*64*768  (1.5 GB)
__device__ float g_aout[134217728];  // 8192*64*256  (512 MB)

__device__ __forceinline__ void mma_f16(float* d, const unsigned* a, const unsigned* b) {
    asm volatile(
        "mma.sync.aligned.m16n8k16.row.col.f32.f16.f16.f32 "
        "{%0,%1,%2,%3}, {%4,%5,%6,%7}, {%8,%9}, {%0,%1,%2,%3};"
        : "+f"(d[0]), "+f"(d[1]), "+f"(d[2]), "+f"(d[3])
        : "r"(a[0]), "r"(a[1]), "r"(a[2]), "r"(a[3]), "r"(b[0]), "r"(b[1]));
}

__device__ __forceinline__ unsigned pack2(float x, float y) {
    __half2 h = __floats2half2_rn(x, y);
    return *(unsigned*)&h;
}

#define PADH 40                          // halfs per smem row (80 B)
#define A_H  (128 * PADH)                // 5120 halfs
#define B_H  (64 * PADH)                 // 2560 halfs
#define STAGE_H (A_H + B_H)              // 7680 halfs / stage (15360 B)

__global__ void __launch_bounds__(256, 2)
gemm_f16_kernel(const float* __restrict__ A, const float* __restrict__ W,
                const float* __restrict__ bias, float* __restrict__ C, int Nc)
{
    extern __shared__ __half sm[];

    const int t    = threadIdx.x;
    const int lane = t & 31;
    const int gid  = lane >> 2;
    const int tig  = lane & 3;
    const int w    = t >> 5;
    const int wm   = w & 3;              // 4 warps in m
    const int wn   = w >> 2;             // 2 warps in n
    const size_t mBase = (size_t)blockIdx.y * 128;
    const int    nBase = blockIdx.x * 64;

    // global load mapping
    const int arow = t >> 1;             // 0..127
    const int acol = (t & 1) << 4;       // 0 / 16
    const int brow = t >> 2;             // 0..63
    const int bcol = (t & 3) << 3;       // 0,8,16,24

    const float* Ap = A + (mBase + arow) * 256 + acol;
    const float* Wp = W + ((size_t)nBase + brow) * 256 + bcol;

    float acc[2][4][4];
#pragma unroll
    for (int mt = 0; mt < 2; mt++)
#pragma unroll
        for (int nt = 0; nt < 4; nt++)
#pragma unroll
            for (int i = 0; i < 4; i++) acc[mt][nt][i] = 0.f;

    float4 ar[4], br[2];
#pragma unroll
    for (int i = 0; i < 4; i++) ar[i] = *(const float4*)(Ap + (i << 2));
#pragma unroll
    for (int i = 0; i < 2; i++) br[i] = *(const float4*)(Wp + (i << 2));

    auto stage_store = [&](int s, const float4* a4, const float4* b4) {
        __half* as = sm + s * STAGE_H;
        __half* bs = as + A_H;
        uint4 u;
        u.x = pack2(a4[0].x, a4[0].y); u.y = pack2(a4[0].z, a4[0].w);
        u.z = pack2(a4[1].x, a4[1].y); u.w = pack2(a4[1].z, a4[1].w);
        *(uint4*)(as + arow * PADH + acol) = u;
        u.x = pack2(a4[2].x, a4[2].y); u.y = pack2(a4[2].z, a4[2].w);
        u.z = pack2(a4[3].x, a4[3].y); u.w = pack2(a4[3].z, a4[3].w);
        *(uint4*)(as + arow * PADH + acol + 8) = u;
        u.x = pack2(b4[0].x, b4[0].y); u.y = pack2(b4[0].z, b4[0].w);
        u.z = pack2(b4[1].x, b4[1].y); u.w = pack2(b4[1].z, b4[1].w);
        *(uint4*)(bs + brow * PADH + bcol) = u;
    };

    stage_store(0, ar, br);

#pragma unroll 2
    for (int it = 0; it < 8; it++) {
        __syncthreads();  // stage (it&1) visible; previous stage's reads done

        if (it + 1 < 8) {
            const int k0 = (it + 1) << 5;
#pragma unroll
            for (int i = 0; i < 4; i++) ar[i] = *(const float4*)(Ap + k0 + (i << 2));
#pragma unroll
            for (int i = 0; i < 2; i++) br[i] = *(const float4*)(Wp + k0 + (i << 2));
        }

        const __half* as = sm + (it & 1) * STAGE_H;
        const __half* bs = as + A_H;

#pragma unroll
        for (int kk = 0; kk < 2; kk++) {           // two k16 steps per BK=32
            const int kb = (kk << 4) + (tig << 1); // k offset: kk*16 + 2*tig
            unsigned af[2][4], bf[4][2];
#pragma unroll
            for (int mt = 0; mt < 2; mt++) {
                const __half* r0 = as + (wm * 32 + mt * 16 + gid) * PADH + kb;
                af[mt][0] = *(const unsigned*)(r0);
                af[mt][1] = *(const unsigned*)(r0 + 8 * PADH);
                af[mt][2] = *(const unsigned*)(r0 + 8);
                af[mt][3] = *(const unsigned*)(r0 + 8 * PADH + 8);
            }
#pragma unroll
            for (int nt = 0; nt < 4; nt++) {
                const __half* r0 = bs + (wn * 32 + nt * 8 + gid) * PADH + kb;
                bf[nt][0] = *(const unsigned*)(r0);
                bf[nt][1] = *(const unsigned*)(r0 + 8);
            }
#pragma unroll
            for (int mt = 0; mt < 2; mt++)
#pragma unroll
                for (int nt = 0; nt < 4; nt++)
                    mma_f16(acc[mt][nt], af[mt], bf[nt]);
        }

        if (it + 1 < 8)
            stage_store((it + 1) & 1, ar, br);     // opposite buffer
    }

    // ---- epilogue: + bias, float2 stores
#pragma unroll
    for (int mt = 0; mt < 2; mt++) {
#pragma unroll
        for (int nt = 0; nt < 4; nt++) {
            int col = nBase + wn * 32 + nt * 8 + (tig << 1);
            float b0 = bias[col], b1 = bias[col + 1];
            size_t r0 = mBase + wm * 32 + mt * 16 + gid;
            *(float2*)(C + r0 * Nc + col) =
                make_float2(acc[mt][nt][0] + b0, acc[mt][nt][1] + b1);
            *(float2*)(C + (r0 + 8) * Nc + col) =
                make_float2(acc[mt][nt][2] + b0, acc[mt][nt][3] + b1);
        }
    }
}

// ---------------------------------------------------------------------------
// Attention: one CTA per (head, window). fp32 path (unchanged).
// ---------------------------------------------------------------------------
__global__ void __launch_bounds__(128)
attn_kernel(const float* __restrict__ qkv, const float* __restrict__ table,
            const int* __restrict__ rpi, float* __restrict__ aout)
{
    __shared__ float sq[64][36];
    __shared__ float sk[64][36];
    __shared__ float sv[64][36];
    __shared__ float sp[64][65];

    const int h = blockIdx.x;
    const int b = blockIdx.y;
    const int t = threadIdx.x;

    const float* base = qkv + (size_t)b * 64 * 768 + h * 32;
    for (int idx = t; idx < 64 * 8; idx += 128) {
        int n  = idx >> 3;
        int c4 = (idx & 7) << 2;
        const float* rp = base + n * 768 + c4;
        float4 q4 = *(const float4*)(rp);
        float4 k4 = *(const float4*)(rp + 256);
        float4 v4 = *(const float4*)(rp + 512);
        *(float4*)&sq[n][c4] = q4;
        *(float4*)&sk[n][c4] = k4;
        *(float4*)&sv[n][c4] = v4;
    }
    __syncthreads();

    const int n    = t & 63;
    const int half = t >> 6;

    float qreg[32];
#pragma unroll
    for (int d4 = 0; d4 < 8; d4++) {
        float4 q4 = *(const float4*)&sq[n][d4 << 2];
        qreg[d4 * 4 + 0] = q4.x; qreg[d4 * 4 + 1] = q4.y;
        qreg[d4 * 4 + 2] = q4.z; qreg[d4 * 4 + 3] = q4.w;
    }

    const float scale = 0.17677669529663687f;
#pragma unroll 4
    for (int mm = 0; mm < 32; mm++) {
        int m = (half << 5) + mm;
        float s = 0.f;
#pragma unroll
        for (int d4 = 0; d4 < 8; d4++) {
            float4 k4 = *(const float4*)&sk[m][d4 << 2];
            s += qreg[d4 * 4 + 0] * k4.x + qreg[d4 * 4 + 1] * k4.y
               + qreg[d4 * 4 + 2] * k4.z + qreg[d4 * 4 + 3] * k4.w;
        }
        int idx = rpi[n * 64 + m];
        sp[n][m] = s * scale + table[idx * 8 + h];
    }
    __syncthreads();

    if (t < 64) {
        float mx = -1e30f;
#pragma unroll
        for (int m = 0; m < 64; m++) mx = fmaxf(mx, sp[t][m]);
        float sum = 0.f;
#pragma unroll
        for (int m = 0; m < 64; m++) {
            float e = __expf(sp[t][m] - mx);
            sp[t][m] = e;
            sum += e;
        }
        float inv = 1.f / sum;
#pragma unroll
        for (int m = 0; m < 64; m++) sp[t][m] *= inv;
    }
    __syncthreads();

    float o[16];
#pragma unroll
    for (int i = 0; i < 16; i++) o[i] = 0.f;
    const int dBase = half << 4;
    for (int m = 0; m < 64; m++) {
        float p = sp[n][m];
#pragma unroll
        for (int d4 = 0; d4 < 4; d4++) {
            float4 v4 = *(const float4*)&sv[m][dBase + (d4 << 2)];
            o[d4 * 4 + 0] += p * v4.x; o[d4 * 4 + 1] += p * v4.y;
            o[d4 * 4 + 2] += p * v4.z; o[d4 * 4 + 3] += p * v4.w;
        }
    }
    float* op = aout + ((size_t)b * 64 + n) * 256 + h * 32 + dBase;
#pragma unroll
    for (int d4 = 0; d4 < 4; d4++)
        *(float4*)(op + (d4 << 2)) =
            make_float4(o[d4 * 4 + 0], o[d4 * 4 + 1], o[d4 * 4 + 2], o[d4 * 4 + 3]);
}

// ---------------------------------------------------------------------------
extern "C" void kernel_launch(void* const* d_in, const int* in_sizes, int n_in,
                              void* d_out, int out_size)
{
    const float* x   = (const float*)d_in[0];
    const float* qw  = (const float*)d_in[1];
    const float* qb  = (const float*)d_in[2];
    const float* pw  = (const float*)d_in[3];
    const float* pb  = (const float*)d_in[4];
    const float* tab = (const float*)d_in[5];
    const int*   rpi = (const int*)d_in[6];
    float* out = (float*)d_out;

    float* qkv  = nullptr;
    float* aout = nullptr;
    cudaGetSymbolAddress((void**)&qkv,  g_qkv);
    cudaGetSymbolAddress((void**)&aout, g_aout);

    const int smemBytes = 2 * STAGE_H * sizeof(__half);  // 30720 B
    cudaFuncSetAttribute(gemm_f16_kernel,
                         cudaFuncAttributeMaxDynamicSharedMemorySize, smemBytes);

    // QKV projection: [524288,256] @ [768,256]^T + b
    dim3 g1(768 / 64, (8192 * 64) / 128);   // (12, 4096)
    gemm_f16_kernel<<<g1, 256, smemBytes>>>(x, qw, qb, qkv, 768);

    // Windowed attention
    dim3 g2(8, 8192);
    attn_kernel<<<g2, 128>>>(qkv, tab, rpi, aout);

    // Output projection: [524288,256] @ [256,256]^T + b
    dim3 g3(256 / 64, (8192 * 64) / 128);   // (4, 4096)
    gemm_f16_kernel<<<g3, 256, smemBytes>>>(aout, pw, pb, out, 256);
}

// round 8
// speedup vs baseline: 1.6856x; 1.6856x over previous
#include <cuda_runtime.h>
#include <cuda_fp16.h>
#include <cstdint>

// ---------------------------------------------------------------------------
// LeWinAttention round 8 (= round 7 resubmit after infra failure):
// fp16 mma.sync m16n8k16 GEMMs fed by ldmatrix.x4.
// CTA tile 128x64, BK=32, 2-stage smem double buffer, XOR-swizzled 64B rows.
// ---------------------------------------------------------------------------

__device__ float g_qkv[402653184];   // 8192*64*768  (1.5 GB)
__device__ float g_aout[134217728];  // 8192*64*256  (512 MB)

__device__ __forceinline__ void mma_f16(float* d, const unsigned* a, const unsigned* b) {
    asm volatile(
        "mma.sync.aligned.m16n8k16.row.col.f32.f16.f16.f32 "
        "{%0,%1,%2,%3}, {%4,%5,%6,%7}, {%8,%9}, {%0,%1,%2,%3};"
        : "+f"(d[0]), "+f"(d[1]), "+f"(d[2]), "+f"(d[3])
        : "r"(a[0]), "r"(a[1]), "r"(a[2]), "r"(a[3]), "r"(b[0]), "r"(b[1]));
}
__device__ __forceinline__ void ldsm4(unsigned& r0, unsigned& r1, unsigned& r2,
                                      unsigned& r3, uint32_t addr) {
    asm volatile("ldmatrix.sync.aligned.m8n8.x4.shared.b16 {%0,%1,%2,%3}, [%4];"
                 : "=r"(r0), "=r"(r1), "=r"(r2), "=r"(r3) : "r"(addr));
}
__device__ __forceinline__ unsigned pack2(float x, float y) {
    __half2 h = __floats2half2_rn(x, y);
    return *(unsigned*)&h;
}

// stage: A[128][32h] (8192 B) + B[64][32h] (4096 B); 64 B rows, 16B-chunk
// swizzle chunk' = chunk ^ ((row>>1)&3)  -> LDSM & STS conflict-free.
#define A_BYTES 8192
#define STAGE_B 12288

__global__ void __launch_bounds__(256, 2)
gemm_f16_kernel(const float* __restrict__ A, const float* __restrict__ W,
                const float* __restrict__ bias, float* __restrict__ C, int Nc)
{
    extern __shared__ char sm[];
    uint32_t sbase;
    asm("{ .reg .u64 t; cvta.to.shared.u64 t, %1; cvt.u32.u64 %0, t; }"
        : "=r"(sbase) : "l"(sm));

    const int t    = threadIdx.x;
    const int lane = t & 31;
    const int gid  = lane >> 2;
    const int tig  = lane & 3;
    const int w    = t >> 5;
    const int wm   = w & 3;              // 4 warps in m
    const int wn   = w >> 2;             // 2 warps in n
    const size_t mBase = (size_t)blockIdx.y * 128;
    const int    nBase = blockIdx.x * 64;

    // global load mapping: A row=t>>1, 16 floats at (t&1)*16; B row=t>>2, 8 at (t&3)*8
    const int arow = t >> 1;
    const int acol = (t & 1) << 4;
    const int brow = t >> 2;
    const int bcol = (t & 3) << 3;
    const float* Ap = A + (mBase + arow) * 256 + acol;
    const float* Wp = W + ((size_t)nBase + brow) * 256 + bcol;

    // ---- smem store byte offsets (swizzled)
    const int aswz = (arow >> 1) & 3;
    const uint32_t aoff0 = arow * 64 + ((((t & 1) << 1) ^ aswz) << 4);       // chunk c
    const uint32_t aoff1 = aoff0 ^ 16;                                        // chunk c|1
    const uint32_t boff  = A_BYTES + brow * 64 + (((t & 3) ^ ((brow >> 1) & 3)) << 4);

    // ---- ldmatrix source addresses (kk=0; kk=1 is ^32)
    uint32_t aAddr[2], bAddr[2];
#pragma unroll
    for (int mt = 0; mt < 2; mt++) {
        int row = wm * 32 + mt * 16 + ((lane >> 3) & 1) * 8 + (lane & 7);
        aAddr[mt] = sbase + row * 64 + ((((lane >> 4) ^ ((row >> 1) & 3))) << 4);
    }
#pragma unroll
    for (int q = 0; q < 2; q++) {
        int n = wn * 32 + q * 16 + ((lane >> 4) << 3) + (lane & 7);
        bAddr[q] = sbase + A_BYTES + n * 64
                 + ((((lane >> 3) & 1) ^ ((n >> 1) & 3)) << 4);
    }

    float acc[2][4][4];
#pragma unroll
    for (int mt = 0; mt < 2; mt++)
#pragma unroll
        for (int nt = 0; nt < 4; nt++)
#pragma unroll
            for (int i = 0; i < 4; i++) acc[mt][nt][i] = 0.f;

    float4 ar[4], br[2];
#pragma unroll
    for (int i = 0; i < 4; i++) ar[i] = *(const float4*)(Ap + (i << 2));
#pragma unroll
    for (int i = 0; i < 2; i++) br[i] = *(const float4*)(Wp + (i << 2));

    auto stage_store = [&](int s, const float4* a4, const float4* b4) {
        char* base = sm + s * STAGE_B;
        uint4 u;
        u.x = pack2(a4[0].x, a4[0].y); u.y = pack2(a4[0].z, a4[0].w);
        u.z = pack2(a4[1].x, a4[1].y); u.w = pack2(a4[1].z, a4[1].w);
        *(uint4*)(base + aoff0) = u;
        u.x = pack2(a4[2].x, a4[2].y); u.y = pack2(a4[2].z, a4[2].w);
        u.z = pack2(a4[3].x, a4[3].y); u.w = pack2(a4[3].z, a4[3].w);
        *(uint4*)(base + aoff1) = u;
        u.x = pack2(b4[0].x, b4[0].y); u.y = pack2(b4[0].z, b4[0].w);
        u.z = pack2(b4[1].x, b4[1].y); u.w = pack2(b4[1].z, b4[1].w);
        *(uint4*)(base + boff) = u;
    };

    stage_store(0, ar, br);

#pragma unroll 2
    for (int it = 0; it < 8; it++) {
        __syncthreads();  // stage (it&1) visible; previous stage's reads retired

        if (it + 1 < 8) {
            const int k0 = (it + 1) << 5;
#pragma unroll
            for (int i = 0; i < 4; i++) ar[i] = *(const float4*)(Ap + k0 + (i << 2));
#pragma unroll
            for (int i = 0; i < 2; i++) br[i] = *(const float4*)(Wp + k0 + (i << 2));
        }

        const uint32_t so = (it & 1) * STAGE_B;

#pragma unroll
        for (int kk = 0; kk < 2; kk++) {
            const uint32_t kx = kk << 5;  // chunk bit1 = 32 B
            unsigned af[2][4], bf[4][2];
#pragma unroll
            for (int mt = 0; mt < 2; mt++)
                ldsm4(af[mt][0], af[mt][1], af[mt][2], af[mt][3],
                      (aAddr[mt] + so) ^ kx);
#pragma unroll
            for (int q = 0; q < 2; q++)
                ldsm4(bf[2 * q][0], bf[2 * q][1], bf[2 * q + 1][0], bf[2 * q + 1][1],
                      (bAddr[q] + so) ^ kx);
#pragma unroll
            for (int mt = 0; mt < 2; mt++)
#pragma unroll
                for (int nt = 0; nt < 4; nt++)
                    mma_f16(acc[mt][nt], af[mt], bf[nt]);
        }

        if (it + 1 < 8)
            stage_store((it + 1) & 1, ar, br);  // opposite buffer
    }

    // ---- epilogue: + bias, float2 stores
#pragma unroll
    for (int mt = 0; mt < 2; mt++) {
#pragma unroll
        for (int nt = 0; nt < 4; nt++) {
            int col = nBase + wn * 32 + nt * 8 + (tig << 1);
            float b0 = bias[col], b1 = bias[col + 1];
            size_t r0 = mBase + wm * 32 + mt * 16 + gid;
            *(float2*)(C + r0 * Nc + col) =
                make_float2(acc[mt][nt][0] + b0, acc[mt][nt][1] + b1);
            *(float2*)(C + (r0 + 8) * Nc + col) =
                make_float2(acc[mt][nt][2] + b0, acc[mt][nt][3] + b1);
        }
    }
}

// ---------------------------------------------------------------------------
// Attention: one CTA per (head, window). fp32 path (unchanged).
// ---------------------------------------------------------------------------
__global__ void __launch_bounds__(128)
attn_kernel(const float* __restrict__ qkv, const float* __restrict__ table,
            const int* __restrict__ rpi, float* __restrict__ aout)
{
    __shared__ float sq[64][36];
    __shared__ float sk[64][36];
    __shared__ float sv[64][36];
    __shared__ float sp[64][65];

    const int h = blockIdx.x;
    const int b = blockIdx.y;
    const int t = threadIdx.x;

    const float* base = qkv + (size_t)b * 64 * 768 + h * 32;
    for (int idx = t; idx < 64 * 8; idx += 128) {
        int n  = idx >> 3;
        int c4 = (idx & 7) << 2;
        const float* rp = base + n * 768 + c4;
        float4 q4 = *(const float4*)(rp);
        float4 k4 = *(const float4*)(rp + 256);
        float4 v4 = *(const float4*)(rp + 512);
        *(float4*)&sq[n][c4] = q4;
        *(float4*)&sk[n][c4] = k4;
        *(float4*)&sv[n][c4] = v4;
    }
    __syncthreads();

    const int n    = t & 63;
    const int half = t >> 6;

    float qreg[32];
#pragma unroll
    for (int d4 = 0; d4 < 8; d4++) {
        float4 q4 = *(const float4*)&sq[n][d4 << 2];
        qreg[d4 * 4 + 0] = q4.x; qreg[d4 * 4 + 1] = q4.y;
        qreg[d4 * 4 + 2] = q4.z; qreg[d4 * 4 + 3] = q4.w;
    }

    const float scale = 0.17677669529663687f;
#pragma unroll 4
    for (int mm = 0; mm < 32; mm++) {
        int m = (half << 5) + mm;
        float s = 0.f;
#pragma unroll
        for (int d4 = 0; d4 < 8; d4++) {
            float4 k4 = *(const float4*)&sk[m][d4 << 2];
            s += qreg[d4 * 4 + 0] * k4.x + qreg[d4 * 4 + 1] * k4.y
               + qreg[d4 * 4 + 2] * k4.z + qreg[d4 * 4 + 3] * k4.w;
        }
        int idx = rpi[n * 64 + m];
        sp[n][m] = s * scale + table[idx * 8 + h];
    }
    __syncthreads();

    if (t < 64) {
        float mx = -1e30f;
#pragma unroll
        for (int m = 0; m < 64; m++) mx = fmaxf(mx, sp[t][m]);
        float sum = 0.f;
#pragma unroll
        for (int m = 0; m < 64; m++) {
            float e = __expf(sp[t][m] - mx);
            sp[t][m] = e;
            sum += e;
        }
        float inv = 1.f / sum;
#pragma unroll
        for (int m = 0; m < 64; m++) sp[t][m] *= inv;
    }
    __syncthreads();

    float o[16];
#pragma unroll
    for (int i = 0; i < 16; i++) o[i] = 0.f;
    const int dBase = half << 4;
    for (int m = 0; m < 64; m++) {
        float p = sp[n][m];
#pragma unroll
        for (int d4 = 0; d4 < 4; d4++) {
            float4 v4 = *(const float4*)&sv[m][dBase + (d4 << 2)];
            o[d4 * 4 + 0] += p * v4.x; o[d4 * 4 + 1] += p * v4.y;
            o[d4 * 4 + 2] += p * v4.z; o[d4 * 4 + 3] += p * v4.w;
        }
    }
    float* op = aout + ((size_t)b * 64 + n) * 256 + h * 32 + dBase;
#pragma unroll
    for (int d4 = 0; d4 < 4; d4++)
        *(float4*)(op + (d4 << 2)) =
            make_float4(o[d4 * 4 + 0], o[d4 * 4 + 1], o[d4 * 4 + 2], o[d4 * 4 + 3]);
}

// ---------------------------------------------------------------------------
extern "C" void kernel_launch(void* const* d_in, const int* in_sizes, int n_in,
                              void* d_out, int out_size)
{
    const float* x   = (const float*)d_in[0];
    const float* qw  = (const float*)d_in[1];
    const float* qb  = (const float*)d_in[2];
    const float* pw  = (const float*)d_in[3];
    const float* pb  = (const float*)d_in[4];
    const float* tab = (const float*)d_in[5];
    const int*   rpi = (const int*)d_in[6];
    float* out = (float*)d_out;

    float* qkv  = nullptr;
    float* aout = nullptr;
    cudaGetSymbolAddress((void**)&qkv,  g_qkv);
    cudaGetSymbolAddress((void**)&aout, g_aout);

    const int smemBytes = 2 * STAGE_B;  // 24576 B
    cudaFuncSetAttribute(gemm_f16_kernel,
                         cudaFuncAttributeMaxDynamicSharedMemorySize, smemBytes);

    // QKV projection: [524288,256] @ [768,256]^T + b
    dim3 g1(768 / 64, (8192 * 64) / 128);   // (12, 4096)
    gemm_f16_kernel<<<g1, 256, smemBytes>>>(x, qw, qb, qkv, 768);

    // Windowed attention
    dim3 g2(8, 8192);
    attn_kernel<<<g2, 128>>>(qkv, tab, rpi, aout);

    // Output projection: [524288,256] @ [256,256]^T + b
    dim3 g3(256 / 64, (8192 * 64) / 128);   // (4, 4096)
    gemm_f16_kernel<<<g3, 256, smemBytes>>>(aout, pw, pb, out, 256);
}

// round 10
// speedup vs baseline: 2.1540x; 1.2778x over previous
#include <cuda_runtime.h>
#include <cuda_fp16.h>
#include <cstdint>

// ---------------------------------------------------------------------------
// LeWinAttention round 10 (= round 9 resubmit after infra failure):
// all-fp16 dataflow + cp.async 4-stage GEMM pipeline.
//   convert(x,W) -> fp16 ; gemm_cp<half>(qkv) ; attn(fp16 io) ; gemm_cp<float>
// ---------------------------------------------------------------------------

__device__ __half g_xh[134217728];    // x fp16          (256 MB)
__device__ __half g_qkvh[402653184];  // qkv fp16        (768 MB)
__device__ __half g_aouth[134217728]; // attn out fp16   (256 MB)
__device__ __half g_wh[262144];       // qkv_w (196608) + proj_w (65536)

// ---------------- helpers --------------------------------------------------
__device__ __forceinline__ void mma_f16(float* d, const unsigned* a, const unsigned* b) {
    asm volatile(
        "mma.sync.aligned.m16n8k16.row.col.f32.f16.f16.f32 "
        "{%0,%1,%2,%3}, {%4,%5,%6,%7}, {%8,%9}, {%0,%1,%2,%3};"
        : "+f"(d[0]), "+f"(d[1]), "+f"(d[2]), "+f"(d[3])
        : "r"(a[0]), "r"(a[1]), "r"(a[2]), "r"(a[3]), "r"(b[0]), "r"(b[1]));
}
__device__ __forceinline__ void ldsm4(unsigned& r0, unsigned& r1, unsigned& r2,
                                      unsigned& r3, uint32_t addr) {
    asm volatile("ldmatrix.sync.aligned.m8n8.x4.shared.b16 {%0,%1,%2,%3}, [%4];"
                 : "=r"(r0), "=r"(r1), "=r"(r2), "=r"(r3) : "r"(addr));
}
__device__ __forceinline__ void cpasync16(uint32_t dst, const void* src) {
    asm volatile("cp.async.cg.shared.global [%0], [%1], 16;" :: "r"(dst), "l"(src));
}
#define CP_COMMIT() asm volatile("cp.async.commit_group;" ::: "memory")
#define CP_WAIT2()  asm volatile("cp.async.wait_group 2;" ::: "memory")

__device__ __forceinline__ void store2(float* p, float v0, float v1) {
    *(float2*)p = make_float2(v0, v1);
}
__device__ __forceinline__ void store2(__half* p, float v0, float v1) {
    *(__half2*)p = __floats2half2_rn(v0, v1);
}

// ---------------------------------------------------------------------------
// fp32 -> fp16 conversion (grid-stride over float4 groups)
// ---------------------------------------------------------------------------
__global__ void f2h_kernel(const float* __restrict__ in, __half* __restrict__ out, int n4)
{
    for (int i = blockIdx.x * blockDim.x + threadIdx.x; i < n4;
         i += gridDim.x * blockDim.x) {
        float4 v = *(const float4*)(in + (size_t)i * 4);
        __half2 h0 = __floats2half2_rn(v.x, v.y);
        __half2 h1 = __floats2half2_rn(v.z, v.w);
        uint2 u;
        u.x = *(unsigned*)&h0; u.y = *(unsigned*)&h1;
        *(uint2*)(out + (size_t)i * 4) = u;
    }
}

// ---------------------------------------------------------------------------
// GEMM: C[M,Nc] = A_h[M,256] @ W_h[Nc,256]^T + bias   (fp16 mma, cp.async x4)
// CTA 128x64, BK=32, 4 stages (3 in flight). Stage: A 8KB + B 4KB = 12KB.
// swizzle: 16B chunk' = chunk ^ ((row>>1)&3)  (LDSM & cp.async-dst conflict-free)
// ---------------------------------------------------------------------------
#define A_BYTES 8192
#define STAGE_B 12288
#define NSTAGE  4

template <typename OutT>
__global__ void __launch_bounds__(256, 3)
gemm_cp_kernel(const __half* __restrict__ A, const __half* __restrict__ W,
               const float* __restrict__ bias, OutT* __restrict__ C, int Nc)
{
    extern __shared__ char sm[];
    uint32_t sbase;
    asm("{ .reg .u64 t; cvta.to.shared.u64 t, %1; cvt.u32.u64 %0, t; }"
        : "=r"(sbase) : "l"(sm));

    const int t    = threadIdx.x;
    const int lane = t & 31;
    const int gid  = lane >> 2;
    const int tig  = lane & 3;
    const int w    = t >> 5;
    const int wm   = w & 3;
    const int wn   = w >> 2;
    const size_t mBase = (size_t)blockIdx.y * 128;
    const int    nBase = blockIdx.x * 64;

    // cp.async per-thread mapping: 3 chunks (A rows t>>2 and 64+(t>>2), B row t>>2)
    const int crow = t >> 2;            // 0..63
    const int cc   = t & 3;             // chunk 0..3
    const __half* aSrc0 = A + (mBase + crow) * 256 + cc * 8;
    const __half* aSrc1 = A + (mBase + 64 + crow) * 256 + cc * 8;
    const __half* bSrc  = W + ((size_t)nBase + crow) * 256 + cc * 8;
    const int csw = (cc ^ ((crow >> 1) & 3)) << 4;
    const uint32_t dA0 = sbase + crow * 64 + csw;
    const uint32_t dA1 = sbase + (64 + crow) * 64 + csw;
    const uint32_t dB  = sbase + A_BYTES + crow * 64 + csw;

    // ldmatrix addresses (stage 0; stage s adds s*STAGE_B; kk=1 is ^32)
    uint32_t aAddr[2], bAddr[2];
#pragma unroll
    for (int mt = 0; mt < 2; mt++) {
        int row = wm * 32 + mt * 16 + ((lane >> 3) & 1) * 8 + (lane & 7);
        aAddr[mt] = sbase + row * 64 + ((((lane >> 4) ^ ((row >> 1) & 3))) << 4);
    }
#pragma unroll
    for (int q = 0; q < 2; q++) {
        int n = wn * 32 + q * 16 + ((lane >> 4) << 3) + (lane & 7);
        bAddr[q] = sbase + A_BYTES + n * 64
                 + ((((lane >> 3) & 1) ^ ((n >> 1) & 3)) << 4);
    }

    float acc[2][4][4];
#pragma unroll
    for (int mt = 0; mt < 2; mt++)
#pragma unroll
        for (int nt = 0; nt < 4; nt++)
#pragma unroll
            for (int i = 0; i < 4; i++) acc[mt][nt][i] = 0.f;

    auto issue = [&](int s) {
        const int k0 = s << 5;                      // halfs
        const uint32_t so = (s & 3) * STAGE_B;
        cpasync16(dA0 + so, aSrc0 + k0);
        cpasync16(dA1 + so, aSrc1 + k0);
        cpasync16(dB + so, bSrc + k0);
    };

    // prologue: 3 stages in flight
    issue(0); CP_COMMIT();
    issue(1); CP_COMMIT();
    issue(2); CP_COMMIT();

#pragma unroll
    for (int it = 0; it < 8; it++) {
        CP_WAIT2();          // stage it landed (<=2 younger groups pending)
        __syncthreads();     // all threads' arrivals visible; old reads retired

        const uint32_t so = (it & 3) * STAGE_B;
#pragma unroll
        for (int kk = 0; kk < 2; kk++) {
            const uint32_t kx = kk << 5;
            unsigned af[2][4], bf[4][2];
#pragma unroll
            for (int mt = 0; mt < 2; mt++)
                ldsm4(af[mt][0], af[mt][1], af[mt][2], af[mt][3],
                      (aAddr[mt] + so) ^ kx);
#pragma unroll
            for (int q = 0; q < 2; q++)
                ldsm4(bf[2 * q][0], bf[2 * q][1], bf[2 * q + 1][0], bf[2 * q + 1][1],
                      (bAddr[q] + so) ^ kx);
#pragma unroll
            for (int mt = 0; mt < 2; mt++)
#pragma unroll
                for (int nt = 0; nt < 4; nt++)
                    mma_f16(acc[mt][nt], af[mt], bf[nt]);
        }

        if (it + 3 < 8) issue(it + 3);
        CP_COMMIT();         // exactly one group per iter keeps wait counting exact
    }

    // ---- epilogue: + bias
#pragma unroll
    for (int mt = 0; mt < 2; mt++) {
#pragma unroll
        for (int nt = 0; nt < 4; nt++) {
            int col = nBase + wn * 32 + nt * 8 + (tig << 1);
            float b0 = bias[col], b1 = bias[col + 1];
            size_t r0 = mBase + wm * 32 + mt * 16 + gid;
            store2(C + r0 * Nc + col, acc[mt][nt][0] + b0, acc[mt][nt][1] + b1);
            store2(C + (r0 + 8) * Nc + col, acc[mt][nt][2] + b0, acc[mt][nt][3] + b1);
        }
    }
}

// ---------------------------------------------------------------------------
// Attention: one CTA per (head, window). fp16 gmem io, fp32 math.
// ---------------------------------------------------------------------------
__global__ void __launch_bounds__(128)
attn_kernel(const __half* __restrict__ qkv, const float* __restrict__ table,
            const int* __restrict__ rpi, __half* __restrict__ aout)
{
    __shared__ float sq[64][36];
    __shared__ float sk[64][36];
    __shared__ float sv[64][36];
    __shared__ float sp[64][65];

    const int h = blockIdx.x;
    const int b = blockIdx.y;
    const int t = threadIdx.x;

    const __half* base = qkv + (size_t)b * 64 * 768 + h * 32;
    for (int idx = t; idx < 256; idx += 128) {
        int n  = idx >> 2;
        int c8 = (idx & 3) << 3;                 // 8 halfs = 16 B
        const __half* rp = base + n * 768 + c8;
        uint4 qu = *(const uint4*)(rp);
        uint4 ku = *(const uint4*)(rp + 256);
        uint4 vu = *(const uint4*)(rp + 512);
        const __half2* qh = (const __half2*)&qu;
        const __half2* kh = (const __half2*)&ku;
        const __half2* vh = (const __half2*)&vu;
#pragma unroll
        for (int j = 0; j < 4; j++) {
            float2 qf = __half22float2(qh[j]);
            float2 kf = __half22float2(kh[j]);
            float2 vf = __half22float2(vh[j]);
            sq[n][c8 + 2 * j] = qf.x; sq[n][c8 + 2 * j + 1] = qf.y;
            sk[n][c8 + 2 * j] = kf.x; sk[n][c8 + 2 * j + 1] = kf.y;
            sv[n][c8 + 2 * j] = vf.x; sv[n][c8 + 2 * j + 1] = vf.y;
        }
    }
    __syncthreads();

    const int n    = t & 63;
    const int half_ = t >> 6;

    float qreg[32];
#pragma unroll
    for (int d4 = 0; d4 < 8; d4++) {
        float4 q4 = *(const float4*)&sq[n][d4 << 2];
        qreg[d4 * 4 + 0] = q4.x; qreg[d4 * 4 + 1] = q4.y;
        qreg[d4 * 4 + 2] = q4.z; qreg[d4 * 4 + 3] = q4.w;
    }

    const float scale = 0.17677669529663687f;
#pragma unroll 4
    for (int mm = 0; mm < 32; mm++) {
        int m = (half_ << 5) + mm;
        float s = 0.f;
#pragma unroll
        for (int d4 = 0; d4 < 8; d4++) {
            float4 k4 = *(const float4*)&sk[m][d4 << 2];
            s += qreg[d4 * 4 + 0] * k4.x + qreg[d4 * 4 + 1] * k4.y
               + qreg[d4 * 4 + 2] * k4.z + qreg[d4 * 4 + 3] * k4.w;
        }
        int idx = rpi[n * 64 + m];
        sp[n][m] = s * scale + table[idx * 8 + h];
    }
    __syncthreads();

    if (t < 64) {
        float mx = -1e30f;
#pragma unroll
        for (int m = 0; m < 64; m++) mx = fmaxf(mx, sp[t][m]);
        float sum = 0.f;
#pragma unroll
        for (int m = 0; m < 64; m++) {
            float e = __expf(sp[t][m] - mx);
            sp[t][m] = e;
            sum += e;
        }
        float inv = 1.f / sum;
#pragma unroll
        for (int m = 0; m < 64; m++) sp[t][m] *= inv;
    }
    __syncthreads();

    float o[16];
#pragma unroll
    for (int i = 0; i < 16; i++) o[i] = 0.f;
    const int dBase = half_ << 4;
    for (int m = 0; m < 64; m++) {
        float p = sp[n][m];
#pragma unroll
        for (int d4 = 0; d4 < 4; d4++) {
            float4 v4 = *(const float4*)&sv[m][dBase + (d4 << 2)];
            o[d4 * 4 + 0] += p * v4.x; o[d4 * 4 + 1] += p * v4.y;
            o[d4 * 4 + 2] += p * v4.z; o[d4 * 4 + 3] += p * v4.w;
        }
    }
    __half* op = aout + ((size_t)b * 64 + n) * 256 + h * 32 + dBase;
    uint4 u;
    unsigned* up = (unsigned*)&u;
#pragma unroll
    for (int j = 0; j < 4; j++) {
        __half2 hh = __floats2half2_rn(o[2 * j], o[2 * j + 1]);
        up[j] = *(unsigned*)&hh;
    }
    *(uint4*)op = u;
#pragma unroll
    for (int j = 0; j < 4; j++) {
        __half2 hh = __floats2half2_rn(o[8 + 2 * j], o[9 + 2 * j]);
        up[j] = *(unsigned*)&hh;
    }
    *(uint4*)(op + 8) = u;
}

// ---------------------------------------------------------------------------
extern "C" void kernel_launch(void* const* d_in, const int* in_sizes, int n_in,
                              void* d_out, int out_size)
{
    const float* x   = (const float*)d_in[0];
    const float* qw  = (const float*)d_in[1];
    const float* qb  = (const float*)d_in[2];
    const float* pw  = (const float*)d_in[3];
    const float* pb  = (const float*)d_in[4];
    const float* tab = (const float*)d_in[5];
    const int*   rpi = (const int*)d_in[6];
    float* out = (float*)d_out;

    __half *xh = nullptr, *qkvh = nullptr, *aouth = nullptr, *wh = nullptr;
    cudaGetSymbolAddress((void**)&xh,    g_xh);
    cudaGetSymbolAddress((void**)&qkvh,  g_qkvh);
    cudaGetSymbolAddress((void**)&aouth, g_aouth);
    cudaGetSymbolAddress((void**)&wh,    g_wh);

    const int smemBytes = NSTAGE * STAGE_B;  // 49152 B
    cudaFuncSetAttribute(gemm_cp_kernel<__half>,
                         cudaFuncAttributeMaxDynamicSharedMemorySize, smemBytes);
    cudaFuncSetAttribute(gemm_cp_kernel<float>,
                         cudaFuncAttributeMaxDynamicSharedMemorySize, smemBytes);

    // fp32 -> fp16 conversions
    f2h_kernel<<<32768, 256>>>(x, xh, 134217728 / 4);
    f2h_kernel<<<192, 256>>>(qw, wh, 196608 / 4);
    f2h_kernel<<<64, 256>>>(pw, wh + 196608, 65536 / 4);

    // QKV projection: [524288,256] @ [768,256]^T + b  -> fp16 qkv
    dim3 g1(768 / 64, (8192 * 64) / 128);   // (12, 4096)
    gemm_cp_kernel<__half><<<g1, 256, smemBytes>>>(xh, wh, qb, qkvh, 768);

    // Windowed attention (fp16 io)
    dim3 g2(8, 8192);
    attn_kernel<<<g2, 128>>>(qkvh, tab, rpi, aouth);

    // Output projection: [524288,256] @ [256,256]^T + b -> fp32 out
    dim3 g3(256 / 64, (8192 * 64) / 128);   // (4, 4096)
    gemm_cp_kernel<float><<<g3, 256, smemBytes>>>(aouth, wh + 196608, pb, out, 256);
}

// round 11
// speedup vs baseline: 2.2352x; 1.0377x over previous
#include <cuda_runtime.h>
#include <cuda_fp16.h>
#include <cstdint>

// ---------------------------------------------------------------------------
// LeWinAttention round 11: R10 + MUFU-free softmax (FMA exp, 128-thread split).
// ---------------------------------------------------------------------------

__device__ __half g_xh[134217728];    // x fp16          (256 MB)
__device__ __half g_qkvh[402653184];  // qkv fp16        (768 MB)
__device__ __half g_aouth[134217728]; // attn out fp16   (256 MB)
__device__ __half g_wh[262144];       // qkv_w (196608) + proj_w (65536)

// ---------------- helpers --------------------------------------------------
__device__ __forceinline__ void mma_f16(float* d, const unsigned* a, const unsigned* b) {
    asm volatile(
        "mma.sync.aligned.m16n8k16.row.col.f32.f16.f16.f32 "
        "{%0,%1,%2,%3}, {%4,%5,%6,%7}, {%8,%9}, {%0,%1,%2,%3};"
        : "+f"(d[0]), "+f"(d[1]), "+f"(d[2]), "+f"(d[3])
        : "r"(a[0]), "r"(a[1]), "r"(a[2]), "r"(a[3]), "r"(b[0]), "r"(b[1]));
}
__device__ __forceinline__ void ldsm4(unsigned& r0, unsigned& r1, unsigned& r2,
                                      unsigned& r3, uint32_t addr) {
    asm volatile("ldmatrix.sync.aligned.m8n8.x4.shared.b16 {%0,%1,%2,%3}, [%4];"
                 : "=r"(r0), "=r"(r1), "=r"(r2), "=r"(r3) : "r"(addr));
}
__device__ __forceinline__ void cpasync16(uint32_t dst, const void* src) {
    asm volatile("cp.async.cg.shared.global [%0], [%1], 16;" :: "r"(dst), "l"(src));
}
#define CP_COMMIT() asm volatile("cp.async.commit_group;" ::: "memory")
#define CP_WAIT2()  asm volatile("cp.async.wait_group 2;" ::: "memory")

__device__ __forceinline__ void store2(float* p, float v0, float v1) {
    *(float2*)p = make_float2(v0, v1);
}
__device__ __forceinline__ void store2(__half* p, float v0, float v1) {
    *(__half2*)p = __floats2half2_rn(v0, v1);
}

// FMA-pipe exp (no MUFU): exp(x) for x <= 0. rel err ~2e-6.
__device__ __forceinline__ float fexp(float x) {
    float y = fmaxf(x * 1.4426950408889634f, -126.0f);  // log2(e), clamp
    float r = y + 12582912.0f;                          // 1.5*2^23 round magic
    float k = r - 12582912.0f;
    float f = y - k;                                    // f in [-0.5, 0.5]
    float p = 0.0013333558f;                            // 2^f Taylor (ln2^n/n!)
    p = fmaf(p, f, 0.0096181291f);
    p = fmaf(p, f, 0.0555041087f);
    p = fmaf(p, f, 0.2402264676f);
    p = fmaf(p, f, 0.6931471806f);
    p = fmaf(p, f, 1.0f);
    return __int_as_float(__float_as_int(p) + (((int)k) << 23));
}

// ---------------------------------------------------------------------------
// fp32 -> fp16 conversion (grid-stride over float4 groups)
// ---------------------------------------------------------------------------
__global__ void f2h_kernel(const float* __restrict__ in, __half* __restrict__ out, int n4)
{
    for (int i = blockIdx.x * blockDim.x + threadIdx.x; i < n4;
         i += gridDim.x * blockDim.x) {
        float4 v = *(const float4*)(in + (size_t)i * 4);
        __half2 h0 = __floats2half2_rn(v.x, v.y);
        __half2 h1 = __floats2half2_rn(v.z, v.w);
        uint2 u;
        u.x = *(unsigned*)&h0; u.y = *(unsigned*)&h1;
        *(uint2*)(out + (size_t)i * 4) = u;
    }
}

// ---------------------------------------------------------------------------
// GEMM (unchanged from R10): fp16 mma + cp.async 4-stage pipeline.
// ---------------------------------------------------------------------------
#define A_BYTES 8192
#define STAGE_B 12288
#define NSTAGE  4

template <typename OutT>
__global__ void __launch_bounds__(256, 3)
gemm_cp_kernel(const __half* __restrict__ A, const __half* __restrict__ W,
               const float* __restrict__ bias, OutT* __restrict__ C, int Nc)
{
    extern __shared__ char sm[];
    uint32_t sbase;
    asm("{ .reg .u64 t; cvta.to.shared.u64 t, %1; cvt.u32.u64 %0, t; }"
        : "=r"(sbase) : "l"(sm));

    const int t    = threadIdx.x;
    const int lane = t & 31;
    const int gid  = lane >> 2;
    const int tig  = lane & 3;
    const int w    = t >> 5;
    const int wm   = w & 3;
    const int wn   = w >> 2;
    const size_t mBase = (size_t)blockIdx.y * 128;
    const int    nBase = blockIdx.x * 64;

    const int crow = t >> 2;
    const int cc   = t & 3;
    const __half* aSrc0 = A + (mBase + crow) * 256 + cc * 8;
    const __half* aSrc1 = A + (mBase + 64 + crow) * 256 + cc * 8;
    const __half* bSrc  = W + ((size_t)nBase + crow) * 256 + cc * 8;
    const int csw = (cc ^ ((crow >> 1) & 3)) << 4;
    const uint32_t dA0 = sbase + crow * 64 + csw;
    const uint32_t dA1 = sbase + (64 + crow) * 64 + csw;
    const uint32_t dB  = sbase + A_BYTES + crow * 64 + csw;

    uint32_t aAddr[2], bAddr[2];
#pragma unroll
    for (int mt = 0; mt < 2; mt++) {
        int row = wm * 32 + mt * 16 + ((lane >> 3) & 1) * 8 + (lane & 7);
        aAddr[mt] = sbase + row * 64 + ((((lane >> 4) ^ ((row >> 1) & 3))) << 4);
    }
#pragma unroll
    for (int q = 0; q < 2; q++) {
        int n = wn * 32 + q * 16 + ((lane >> 4) << 3) + (lane & 7);
        bAddr[q] = sbase + A_BYTES + n * 64
                 + ((((lane >> 3) & 1) ^ ((n >> 1) & 3)) << 4);
    }

    float acc[2][4][4];
#pragma unroll
    for (int mt = 0; mt < 2; mt++)
#pragma unroll
        for (int nt = 0; nt < 4; nt++)
#pragma unroll
            for (int i = 0; i < 4; i++) acc[mt][nt][i] = 0.f;

    auto issue = [&](int s) {
        const int k0 = s << 5;
        const uint32_t so = (s & 3) * STAGE_B;
        cpasync16(dA0 + so, aSrc0 + k0);
        cpasync16(dA1 + so, aSrc1 + k0);
        cpasync16(dB + so, bSrc + k0);
    };

    issue(0); CP_COMMIT();
    issue(1); CP_COMMIT();
    issue(2); CP_COMMIT();

#pragma unroll
    for (int it = 0; it < 8; it++) {
        CP_WAIT2();
        __syncthreads();

        const uint32_t so = (it & 3) * STAGE_B;
#pragma unroll
        for (int kk = 0; kk < 2; kk++) {
            const uint32_t kx = kk << 5;
            unsigned af[2][4], bf[4][2];
#pragma unroll
            for (int mt = 0; mt < 2; mt++)
                ldsm4(af[mt][0], af[mt][1], af[mt][2], af[mt][3],
                      (aAddr[mt] + so) ^ kx);
#pragma unroll
            for (int q = 0; q < 2; q++)
                ldsm4(bf[2 * q][0], bf[2 * q][1], bf[2 * q + 1][0], bf[2 * q + 1][1],
                      (bAddr[q] + so) ^ kx);
#pragma unroll
            for (int mt = 0; mt < 2; mt++)
#pragma unroll
                for (int nt = 0; nt < 4; nt++)
                    mma_f16(acc[mt][nt], af[mt], bf[nt]);
        }

        if (it + 3 < 8) issue(it + 3);
        CP_COMMIT();
    }

#pragma unroll
    for (int mt = 0; mt < 2; mt++) {
#pragma unroll
        for (int nt = 0; nt < 4; nt++) {
            int col = nBase + wn * 32 + nt * 8 + (tig << 1);
            float b0 = bias[col], b1 = bias[col + 1];
            size_t r0 = mBase + wm * 32 + mt * 16 + gid;
            store2(C + r0 * Nc + col, acc[mt][nt][0] + b0, acc[mt][nt][1] + b1);
            store2(C + (r0 + 8) * Nc + col, acc[mt][nt][2] + b0, acc[mt][nt][3] + b1);
        }
    }
}

// ---------------------------------------------------------------------------
// Attention: one CTA per (head, window). fp16 io, fp32 math.
// Softmax: FMA exp (no MUFU), 128-thread row-half split, 1/sum folded into o.
// ---------------------------------------------------------------------------
__global__ void __launch_bounds__(128)
attn_kernel(const __half* __restrict__ qkv, const float* __restrict__ table,
            const int* __restrict__ rpi, __half* __restrict__ aout)
{
    __shared__ float sq[64][36];
    __shared__ float sk[64][36];
    __shared__ float sv[64][36];
    __shared__ float sp[64][65];
    __shared__ float smax[64][2];
    __shared__ float ssum[64][2];

    const int h = blockIdx.x;
    const int b = blockIdx.y;
    const int t = threadIdx.x;

    const __half* base = qkv + (size_t)b * 64 * 768 + h * 32;
    for (int idx = t; idx < 256; idx += 128) {
        int n  = idx >> 2;
        int c8 = (idx & 3) << 3;
        const __half* rp = base + n * 768 + c8;
        uint4 qu = *(const uint4*)(rp);
        uint4 ku = *(const uint4*)(rp + 256);
        uint4 vu = *(const uint4*)(rp + 512);
        const __half2* qh = (const __half2*)&qu;
        const __half2* kh = (const __half2*)&ku;
        const __half2* vh = (const __half2*)&vu;
#pragma unroll
        for (int j = 0; j < 4; j++) {
            float2 qf = __half22float2(qh[j]);
            float2 kf = __half22float2(kh[j]);
            float2 vf = __half22float2(vh[j]);
            sq[n][c8 + 2 * j] = qf.x; sq[n][c8 + 2 * j + 1] = qf.y;
            sk[n][c8 + 2 * j] = kf.x; sk[n][c8 + 2 * j + 1] = kf.y;
            sv[n][c8 + 2 * j] = vf.x; sv[n][c8 + 2 * j + 1] = vf.y;
        }
    }
    __syncthreads();

    const int n     = t & 63;
    const int half_ = t >> 6;

    float qreg[32];
#pragma unroll
    for (int d4 = 0; d4 < 8; d4++) {
        float4 q4 = *(const float4*)&sq[n][d4 << 2];
        qreg[d4 * 4 + 0] = q4.x; qreg[d4 * 4 + 1] = q4.y;
        qreg[d4 * 4 + 2] = q4.z; qreg[d4 * 4 + 3] = q4.w;
    }

    const float scale = 0.17677669529663687f;
    float mx = -1e30f;
#pragma unroll 4
    for (int mm = 0; mm < 32; mm++) {
        int m = (half_ << 5) + mm;
        float s = 0.f;
#pragma unroll
        for (int d4 = 0; d4 < 8; d4++) {
            float4 k4 = *(const float4*)&sk[m][d4 << 2];
            s += qreg[d4 * 4 + 0] * k4.x + qreg[d4 * 4 + 1] * k4.y
               + qreg[d4 * 4 + 2] * k4.z + qreg[d4 * 4 + 3] * k4.w;
        }
        int idx = rpi[n * 64 + m];
        s = s * scale + table[idx * 8 + h];
        sp[n][m] = s;
        mx = fmaxf(mx, s);
    }
    smax[n][half_] = mx;
    __syncthreads();

    // exp + partial sums (each thread: its 32-col half of row n)
    mx = fmaxf(smax[n][0], smax[n][1]);
    float sum = 0.f;
#pragma unroll 4
    for (int mm = 0; mm < 32; mm++) {
        int m = (half_ << 5) + mm;
        float e = fexp(sp[n][m] - mx);
        sp[n][m] = e;
        sum += e;
    }
    ssum[n][half_] = sum;
    __syncthreads();

    const float inv = 1.f / (ssum[n][0] + ssum[n][1]);

    // out[n][d] = inv * sum_m p[n][m] * v[m][d]   (thread owns 16 d's)
    float o[16];
#pragma unroll
    for (int i = 0; i < 16; i++) o[i] = 0.f;
    const int dBase = half_ << 4;
    for (int m = 0; m < 64; m++) {
        float p = sp[n][m];
#pragma unroll
        for (int d4 = 0; d4 < 4; d4++) {
            float4 v4 = *(const float4*)&sv[m][dBase + (d4 << 2)];
            o[d4 * 4 + 0] += p * v4.x; o[d4 * 4 + 1] += p * v4.y;
            o[d4 * 4 + 2] += p * v4.z; o[d4 * 4 + 3] += p * v4.w;
        }
    }
    __half* op = aout + ((size_t)b * 64 + n) * 256 + h * 32 + dBase;
    uint4 u;
    unsigned* up = (unsigned*)&u;
#pragma unroll
    for (int j = 0; j < 4; j++) {
        __half2 hh = __floats2half2_rn(o[2 * j] * inv, o[2 * j + 1] * inv);
        up[j] = *(unsigned*)&hh;
    }
    *(uint4*)op = u;
#pragma unroll
    for (int j = 0; j < 4; j++) {
        __half2 hh = __floats2half2_rn(o[8 + 2 * j] * inv, o[9 + 2 * j] * inv);
        up[j] = *(unsigned*)&hh;
    }
    *(uint4*)(op + 8) = u;
}

// ---------------------------------------------------------------------------
extern "C" void kernel_launch(void* const* d_in, const int* in_sizes, int n_in,
                              void* d_out, int out_size)
{
    const float* x   = (const float*)d_in[0];
    const float* qw  = (const float*)d_in[1];
    const float* qb  = (const float*)d_in[2];
    const float* pw  = (const float*)d_in[3];
    const float* pb  = (const float*)d_in[4];
    const float* tab = (const float*)d_in[5];
    const int*   rpi = (const int*)d_in[6];
    float* out = (float*)d_out;

    __half *xh = nullptr, *qkvh = nullptr, *aouth = nullptr, *wh = nullptr;
    cudaGetSymbolAddress((void**)&xh,    g_xh);
    cudaGetSymbolAddress((void**)&qkvh,  g_qkvh);
    cudaGetSymbolAddress((void**)&aouth, g_aouth);
    cudaGetSymbolAddress((void**)&wh,    g_wh);

    const int smemBytes = NSTAGE * STAGE_B;  // 49152 B
    cudaFuncSetAttribute(gemm_cp_kernel<__half>,
                         cudaFuncAttributeMaxDynamicSharedMemorySize, smemBytes);
    cudaFuncSetAttribute(gemm_cp_kernel<float>,
                         cudaFuncAttributeMaxDynamicSharedMemorySize, smemBytes);

    // fp32 -> fp16 conversions
    f2h_kernel<<<32768, 256>>>(x, xh, 134217728 / 4);
    f2h_kernel<<<192, 256>>>(qw, wh, 196608 / 4);
    f2h_kernel<<<64, 256>>>(pw, wh + 196608, 65536 / 4);

    // QKV projection: [524288,256] @ [768,256]^T + b  -> fp16 qkv
    dim3 g1(768 / 64, (8192 * 64) / 128);   // (12, 4096)
    gemm_cp_kernel<__half><<<g1, 256, smemBytes>>>(xh, wh, qb, qkvh, 768);

    // Windowed attention (fp16 io)
    dim3 g2(8, 8192);
    attn_kernel<<<g2, 128>>>(qkvh, tab, rpi, aouth);

    // Output projection: [524288,256] @ [256,256]^T + b -> fp32 out
    dim3 g3(256 / 64, (8192 * 64) / 128);   // (4, 4096)
    gemm_cp_kernel<float><<<g3, 256, smemBytes>>>(aouth, wh + 196608, pb, out, 256);
}

// round 12
// speedup vs baseline: 5.3142x; 2.3775x over previous
#include <cuda_runtime.h>
#include <cuda_fp16.h>
#include <cstdint>

// ---------------------------------------------------------------------------
// LeWinAttention round 12: tensor-core attention (warp-per-head mma) on top of
// R11's cp.async fp16 GEMMs. Bias table precomputed to [8][64][64] fp16.
// ---------------------------------------------------------------------------

__device__ __half g_xh[134217728];    // x fp16          (256 MB)
__device__ __half g_qkvh[402653184];  // qkv fp16        (768 MB)
__device__ __half g_aouth[134217728]; // attn out fp16   (256 MB)
__device__ __half g_wh[262144];       // qkv_w + proj_w
__device__ __half g_biash[32768];     // bias [8][64][64] fp16

// ---------------- helpers --------------------------------------------------
__device__ __forceinline__ void mma_f16(float* d, const unsigned* a, const unsigned* b) {
    asm volatile(
        "mma.sync.aligned.m16n8k16.row.col.f32.f16.f16.f32 "
        "{%0,%1,%2,%3}, {%4,%5,%6,%7}, {%8,%9}, {%0,%1,%2,%3};"
        : "+f"(d[0]), "+f"(d[1]), "+f"(d[2]), "+f"(d[3])
        : "r"(a[0]), "r"(a[1]), "r"(a[2]), "r"(a[3]), "r"(b[0]), "r"(b[1]));
}
__device__ __forceinline__ void ldsm4(unsigned& r0, unsigned& r1, unsigned& r2,
                                      unsigned& r3, uint32_t addr) {
    asm volatile("ldmatrix.sync.aligned.m8n8.x4.shared.b16 {%0,%1,%2,%3}, [%4];"
                 : "=r"(r0), "=r"(r1), "=r"(r2), "=r"(r3) : "r"(addr));
}
__device__ __forceinline__ void ldsm4t(unsigned& r0, unsigned& r1, unsigned& r2,
                                       unsigned& r3, uint32_t addr) {
    asm volatile("ldmatrix.sync.aligned.m8n8.x4.trans.shared.b16 {%0,%1,%2,%3}, [%4];"
                 : "=r"(r0), "=r"(r1), "=r"(r2), "=r"(r3) : "r"(addr));
}
__device__ __forceinline__ void cpasync16(uint32_t dst, const void* src) {
    asm volatile("cp.async.cg.shared.global [%0], [%1], 16;" :: "r"(dst), "l"(src));
}
#define CP_COMMIT() asm volatile("cp.async.commit_group;" ::: "memory")
#define CP_WAIT2()  asm volatile("cp.async.wait_group 2;" ::: "memory")
#define CP_WAIT0()  asm volatile("cp.async.wait_group 0;" ::: "memory")

__device__ __forceinline__ void store2(float* p, float v0, float v1) {
    *(float2*)p = make_float2(v0, v1);
}
__device__ __forceinline__ void store2(__half* p, float v0, float v1) {
    *(__half2*)p = __floats2half2_rn(v0, v1);
}
__device__ __forceinline__ unsigned pack2(float x, float y) {
    __half2 h = __floats2half2_rn(x, y);
    return *(unsigned*)&h;
}

// FMA-pipe exp (no MUFU): exp(x) for x <= 0. rel err ~2e-6.
__device__ __forceinline__ float fexp(float x) {
    float y = fmaxf(x * 1.4426950408889634f, -126.0f);
    float r = y + 12582912.0f;
    float k = r - 12582912.0f;
    float f = y - k;
    float p = 0.0013333558f;
    p = fmaf(p, f, 0.0096181291f);
    p = fmaf(p, f, 0.0555041087f);
    p = fmaf(p, f, 0.2402264676f);
    p = fmaf(p, f, 0.6931471806f);
    p = fmaf(p, f, 1.0f);
    return __int_as_float(__float_as_int(p) + (((int)k) << 23));
}

// ---------------------------------------------------------------------------
__global__ void f2h_kernel(const float* __restrict__ in, __half* __restrict__ out, int n4)
{
    for (int i = blockIdx.x * blockDim.x + threadIdx.x; i < n4;
         i += gridDim.x * blockDim.x) {
        float4 v = *(const float4*)(in + (size_t)i * 4);
        __half2 h0 = __floats2half2_rn(v.x, v.y);
        __half2 h1 = __floats2half2_rn(v.z, v.w);
        uint2 u;
        u.x = *(unsigned*)&h0; u.y = *(unsigned*)&h1;
        *(uint2*)(out + (size_t)i * 4) = u;
    }
}

__global__ void bias_pre_kernel(const float* __restrict__ table,
                                const int* __restrict__ rpi,
                                __half* __restrict__ biash)
{
    int i = blockIdx.x * 256 + threadIdx.x;   // i = n*64 + m
    if (i < 4096) {
        int idx = rpi[i];
#pragma unroll
        for (int h = 0; h < 8; h++)
            biash[h * 4096 + i] = __float2half(table[idx * 8 + h]);
    }
}

// ---------------------------------------------------------------------------
// GEMM (unchanged from R10): fp16 mma + cp.async 4-stage pipeline.
// ---------------------------------------------------------------------------
#define A_BYTES 8192
#define STAGE_B 12288
#define NSTAGE  4

template <typename OutT>
__global__ void __launch_bounds__(256, 3)
gemm_cp_kernel(const __half* __restrict__ A, const __half* __restrict__ W,
               const float* __restrict__ bias, OutT* __restrict__ C, int Nc)
{
    extern __shared__ char sm[];
    uint32_t sbase;
    asm("{ .reg .u64 t; cvta.to.shared.u64 t, %1; cvt.u32.u64 %0, t; }"
        : "=r"(sbase) : "l"(sm));

    const int t    = threadIdx.x;
    const int lane = t & 31;
    const int gid  = lane >> 2;
    const int tig  = lane & 3;
    const int w    = t >> 5;
    const int wm   = w & 3;
    const int wn   = w >> 2;
    const size_t mBase = (size_t)blockIdx.y * 128;
    const int    nBase = blockIdx.x * 64;

    const int crow = t >> 2;
    const int cc   = t & 3;
    const __half* aSrc0 = A + (mBase + crow) * 256 + cc * 8;
    const __half* aSrc1 = A + (mBase + 64 + crow) * 256 + cc * 8;
    const __half* bSrc  = W + ((size_t)nBase + crow) * 256 + cc * 8;
    const int csw = (cc ^ ((crow >> 1) & 3)) << 4;
    const uint32_t dA0 = sbase + crow * 64 + csw;
    const uint32_t dA1 = sbase + (64 + crow) * 64 + csw;
    const uint32_t dB  = sbase + A_BYTES + crow * 64 + csw;

    uint32_t aAddr[2], bAddr[2];
#pragma unroll
    for (int mt = 0; mt < 2; mt++) {
        int row = wm * 32 + mt * 16 + ((lane >> 3) & 1) * 8 + (lane & 7);
        aAddr[mt] = sbase + row * 64 + ((((lane >> 4) ^ ((row >> 1) & 3))) << 4);
    }
#pragma unroll
    for (int q = 0; q < 2; q++) {
        int n = wn * 32 + q * 16 + ((lane >> 4) << 3) + (lane & 7);
        bAddr[q] = sbase + A_BYTES + n * 64
                 + ((((lane >> 3) & 1) ^ ((n >> 1) & 3)) << 4);
    }

    float acc[2][4][4];
#pragma unroll
    for (int mt = 0; mt < 2; mt++)
#pragma unroll
        for (int nt = 0; nt < 4; nt++)
#pragma unroll
            for (int i = 0; i < 4; i++) acc[mt][nt][i] = 0.f;

    auto issue = [&](int s) {
        const int k0 = s << 5;
        const uint32_t so = (s & 3) * STAGE_B;
        cpasync16(dA0 + so, aSrc0 + k0);
        cpasync16(dA1 + so, aSrc1 + k0);
        cpasync16(dB + so, bSrc + k0);
    };

    issue(0); CP_COMMIT();
    issue(1); CP_COMMIT();
    issue(2); CP_COMMIT();

#pragma unroll
    for (int it = 0; it < 8; it++) {
        CP_WAIT2();
        __syncthreads();

        const uint32_t so = (it & 3) * STAGE_B;
#pragma unroll
        for (int kk = 0; kk < 2; kk++) {
            const uint32_t kx = kk << 5;
            unsigned af[2][4], bf[4][2];
#pragma unroll
            for (int mt = 0; mt < 2; mt++)
                ldsm4(af[mt][0], af[mt][1], af[mt][2], af[mt][3],
                      (aAddr[mt] + so) ^ kx);
#pragma unroll
            for (int q = 0; q < 2; q++)
                ldsm4(bf[2 * q][0], bf[2 * q][1], bf[2 * q + 1][0], bf[2 * q + 1][1],
                      (bAddr[q] + so) ^ kx);
#pragma unroll
            for (int mt = 0; mt < 2; mt++)
#pragma unroll
                for (int nt = 0; nt < 4; nt++)
                    mma_f16(acc[mt][nt], af[mt], bf[nt]);
        }

        if (it + 3 < 8) issue(it + 3);
        CP_COMMIT();
    }

#pragma unroll
    for (int mt = 0; mt < 2; mt++) {
#pragma unroll
        for (int nt = 0; nt < 4; nt++) {
            int col = nBase + wn * 32 + nt * 8 + (tig << 1);
            float b0 = bias[col], b1 = bias[col + 1];
            size_t r0 = mBase + wm * 32 + mt * 16 + gid;
            store2(C + r0 * Nc + col, acc[mt][nt][0] + b0, acc[mt][nt][1] + b1);
            store2(C + (r0 + 8) * Nc + col, acc[mt][nt][2] + b0, acc[mt][nt][3] + b1);
        }
    }
}

// ---------------------------------------------------------------------------
// Tensor-core attention: 1 CTA per window, 8 warps = 8 heads.
// smem: full window qkv [64 rows][768 halfs], 16B chunks swizzled by (row&7).
// QK^T via ldmatrix + mma; bias from precomputed table; softmax in regs;
// P.V via pack(C-frag -> A-frag) + ldmatrix.trans for V.
// ---------------------------------------------------------------------------
__global__ void __launch_bounds__(256)
attn_mma_kernel(const __half* __restrict__ qkv, const __half* __restrict__ biash,
                __half* __restrict__ aout)
{
    extern __shared__ char sm[];
    uint32_t sbase;
    asm("{ .reg .u64 t; cvta.to.shared.u64 t, %1; cvt.u32.u64 %0, t; }"
        : "=r"(sbase) : "l"(sm));

    const int b    = blockIdx.x;
    const int t    = threadIdx.x;
    const int lane = t & 31;
    const int h    = t >> 5;           // warp = head
    const int gid  = lane >> 2;
    const int tig  = lane & 3;

    // ---- load window qkv (96 KB): row r = t>>2, chunks (t&3)+4i, swz ^ (r&7)
    {
        const int r = t >> 2;
        const __half* src = qkv + ((size_t)b * 64 + r) * 768 + (t & 3) * 8;
        const uint32_t drow = sbase + r * 1536;
        const int rx = r & 7;
#pragma unroll
        for (int i = 0; i < 24; i++) {
            int cc = (t & 3) + (i << 2);
            cpasync16(drow + ((cc ^ rx) << 4), src + (i << 5));
        }
    }
    CP_COMMIT();
    CP_WAIT0();
    __syncthreads();

    // ---- ldmatrix base addresses (chunk index = seg*4 + c, phys = ck ^ (r&7))
    uint32_t qA, kB, vB;
    {   // Q A-frag (mt=0, ks=0): rows ((lane>>3)&1)*8 + lane&7, c = lane>>4
        int r = ((lane >> 3) & 1) * 8 + (lane & 7);
        int ck = (h << 2) | (lane >> 4);
        qA = sbase + r * 1536 + ((ck ^ (r & 7)) << 4);
    }
    {   // K B-frag (q=0, ks=0): rows ((lane>>4)<<3) + lane&7, c = (lane>>3)&1
        int r = ((lane >> 4) << 3) + (lane & 7);
        int ck = ((8 + h) << 2) | ((lane >> 3) & 1);
        kB = sbase + r * 1536 + ((ck ^ (r & 7)) << 4);
    }
    {   // V trans (ks2=0, ntp=0): tile tt = lane>>3: m = (tt&1)*8 + lane&7, c = tt>>1
        int tt = lane >> 3;
        int r = (tt & 1) * 8 + (lane & 7);
        int ck = ((16 + h) << 2) | (tt >> 1);
        vB = sbase + r * 1536 + ((ck ^ (r & 7)) << 4);
    }

    const float scale = 0.17677669529663687f;
    const __half* bia = biash + h * 4096;

#pragma unroll
    for (int h2 = 0; h2 < 2; h2++) {          // row halves (32 rows each)
        const int mt0 = h2 * 2;

        // ---- QK^T scores
        float sc[2][8][4];
#pragma unroll
        for (int mt = 0; mt < 2; mt++)
#pragma unroll
            for (int nt = 0; nt < 8; nt++)
#pragma unroll
                for (int i = 0; i < 4; i++) sc[mt][nt][i] = 0.f;

        unsigned kf[8][2][2];
#pragma unroll
        for (int ks = 0; ks < 2; ks++)
#pragma unroll
            for (int q = 0; q < 4; q++)
                ldsm4(kf[2 * q][ks][0], kf[2 * q][ks][1],
                      kf[2 * q + 1][ks][0], kf[2 * q + 1][ks][1],
                      (kB + q * 24576) ^ (ks << 5));
#pragma unroll
        for (int mt = 0; mt < 2; mt++)
#pragma unroll
            for (int ks = 0; ks < 2; ks++) {
                unsigned af[4];
                ldsm4(af[0], af[1], af[2], af[3],
                      (qA + (mt0 + mt) * 24576) ^ (ks << 5));
#pragma unroll
                for (int nt = 0; nt < 8; nt++)
                    mma_f16(sc[mt][nt], af, kf[nt][ks]);
            }

        // ---- bias + scale, row max
        float mx0[2], mx1[2];
#pragma unroll
        for (int mt = 0; mt < 2; mt++) {
            float m0 = -1e30f, m1 = -1e30f;
            int row = (mt0 + mt) * 16 + gid;
#pragma unroll
            for (int nt = 0; nt < 8; nt++) {
                float2 b0 = __half22float2(*(const __half2*)(bia + row * 64 + nt * 8 + 2 * tig));
                float2 b1 = __half22float2(*(const __half2*)(bia + (row + 8) * 64 + nt * 8 + 2 * tig));
                sc[mt][nt][0] = fmaf(sc[mt][nt][0], scale, b0.x);
                sc[mt][nt][1] = fmaf(sc[mt][nt][1], scale, b0.y);
                sc[mt][nt][2] = fmaf(sc[mt][nt][2], scale, b1.x);
                sc[mt][nt][3] = fmaf(sc[mt][nt][3], scale, b1.y);
                m0 = fmaxf(m0, fmaxf(sc[mt][nt][0], sc[mt][nt][1]));
                m1 = fmaxf(m1, fmaxf(sc[mt][nt][2], sc[mt][nt][3]));
            }
            m0 = fmaxf(m0, __shfl_xor_sync(0xffffffffu, m0, 1));
            m0 = fmaxf(m0, __shfl_xor_sync(0xffffffffu, m0, 2));
            m1 = fmaxf(m1, __shfl_xor_sync(0xffffffffu, m1, 1));
            m1 = fmaxf(m1, __shfl_xor_sync(0xffffffffu, m1, 2));
            mx0[mt] = m0; mx1[mt] = m1;
        }

        // ---- exp + row sums
        float s0[2], s1[2];
#pragma unroll
        for (int mt = 0; mt < 2; mt++) {
            float a0 = 0.f, a1 = 0.f;
#pragma unroll
            for (int nt = 0; nt < 8; nt++) {
                sc[mt][nt][0] = fexp(sc[mt][nt][0] - mx0[mt]); a0 += sc[mt][nt][0];
                sc[mt][nt][1] = fexp(sc[mt][nt][1] - mx0[mt]); a0 += sc[mt][nt][1];
                sc[mt][nt][2] = fexp(sc[mt][nt][2] - mx1[mt]); a1 += sc[mt][nt][2];
                sc[mt][nt][3] = fexp(sc[mt][nt][3] - mx1[mt]); a1 += sc[mt][nt][3];
            }
            a0 += __shfl_xor_sync(0xffffffffu, a0, 1);
            a0 += __shfl_xor_sync(0xffffffffu, a0, 2);
            a1 += __shfl_xor_sync(0xffffffffu, a1, 1);
            a1 += __shfl_xor_sync(0xffffffffu, a1, 2);
            s0[mt] = a0; s1[mt] = a1;
        }

        // ---- P.V  (A = packed P frags, B = V via ldmatrix.trans)
        float pv[2][4][4];
#pragma unroll
        for (int mt = 0; mt < 2; mt++)
#pragma unroll
            for (int nt = 0; nt < 4; nt++)
#pragma unroll
                for (int i = 0; i < 4; i++) pv[mt][nt][i] = 0.f;

#pragma unroll
        for (int ks2 = 0; ks2 < 4; ks2++) {
            unsigned vb[4][2];
            uint32_t va = vB + ks2 * 24576;
            ldsm4t(vb[0][0], vb[0][1], vb[1][0], vb[1][1], va);
            ldsm4t(vb[2][0], vb[2][1], vb[3][0], vb[3][1], va ^ 32);
#pragma unroll
            for (int mt = 0; mt < 2; mt++) {
                unsigned pf[4];
                pf[0] = pack2(sc[mt][2 * ks2][0],     sc[mt][2 * ks2][1]);
                pf[1] = pack2(sc[mt][2 * ks2][2],     sc[mt][2 * ks2][3]);
                pf[2] = pack2(sc[mt][2 * ks2 + 1][0], sc[mt][2 * ks2 + 1][1]);
                pf[3] = pack2(sc[mt][2 * ks2 + 1][2], sc[mt][2 * ks2 + 1][3]);
#pragma unroll
                for (int nt = 0; nt < 4; nt++)
                    mma_f16(pv[mt][nt], pf, vb[nt]);
            }
        }

        // ---- epilogue: normalize, store fp16
#pragma unroll
        for (int mt = 0; mt < 2; mt++) {
            float i0 = 1.f / s0[mt], i1 = 1.f / s1[mt];
            int row = (mt0 + mt) * 16 + gid;
            __half* o0 = aout + ((size_t)b * 64 + row) * 256 + h * 32 + 2 * tig;
            __half* o1 = o0 + 8 * 256;
#pragma unroll
            for (int nt = 0; nt < 4; nt++) {
                *(__half2*)(o0 + nt * 8) =
                    __floats2half2_rn(pv[mt][nt][0] * i0, pv[mt][nt][1] * i0);
                *(__half2*)(o1 + nt * 8) =
                    __floats2half2_rn(pv[mt][nt][2] * i1, pv[mt][nt][3] * i1);
            }
        }
    }
}

// ---------------------------------------------------------------------------
extern "C" void kernel_launch(void* const* d_in, const int* in_sizes, int n_in,
                              void* d_out, int out_size)
{
    const float* x   = (const float*)d_in[0];
    const float* qw  = (const float*)d_in[1];
    const float* qb  = (const float*)d_in[2];
    const float* pw  = (const float*)d_in[3];
    const float* pb  = (const float*)d_in[4];
    const float* tab = (const float*)d_in[5];
    const int*   rpi = (const int*)d_in[6];
    float* out = (float*)d_out;

    __half *xh = nullptr, *qkvh = nullptr, *aouth = nullptr, *wh = nullptr, *bh = nullptr;
    cudaGetSymbolAddress((void**)&xh,    g_xh);
    cudaGetSymbolAddress((void**)&qkvh,  g_qkvh);
    cudaGetSymbolAddress((void**)&aouth, g_aouth);
    cudaGetSymbolAddress((void**)&wh,    g_wh);
    cudaGetSymbolAddress((void**)&bh,    g_biash);

    const int smemBytes = NSTAGE * STAGE_B;  // 49152 B
    cudaFuncSetAttribute(gemm_cp_kernel<__half>,
                         cudaFuncAttributeMaxDynamicSharedMemorySize, smemBytes);
    cudaFuncSetAttribute(gemm_cp_kernel<float>,
                         cudaFuncAttributeMaxDynamicSharedMemorySize, smemBytes);
    const int attnSmem = 98304;              // 96 KB
    cudaFuncSetAttribute(attn_mma_kernel,
                         cudaFuncAttributeMaxDynamicSharedMemorySize, attnSmem);

    // fp32 -> fp16 conversions + bias table
    f2h_kernel<<<32768, 256>>>(x, xh, 134217728 / 4);
    f2h_kernel<<<192, 256>>>(qw, wh, 196608 / 4);
    f2h_kernel<<<64, 256>>>(pw, wh + 196608, 65536 / 4);
    bias_pre_kernel<<<16, 256>>>(tab, rpi, bh);

    // QKV projection: [524288,256] @ [768,256]^T + b  -> fp16 qkv
    dim3 g1(768 / 64, (8192 * 64) / 128);   // (12, 4096)
    gemm_cp_kernel<__half><<<g1, 256, smemBytes>>>(xh, wh, qb, qkvh, 768);

    // Tensor-core windowed attention (fp16 io)
    attn_mma_kernel<<<8192, 256, attnSmem>>>(qkvh, bh, aouth);

    // Output projection: [524288,256] @ [256,256]^T + b -> fp32 out
    dim3 g3(256 / 64, (8192 * 64) / 128);   // (4, 4096)
    gemm_cp_kernel<float><<<g3, 256, smemBytes>>>(aouth, wh + 196608, pb, out, 256);
}

// round 13
// speedup vs baseline: 5.7946x; 1.0904x over previous
#include <cuda_runtime.h>
#include <cuda_fp16.h>
#include <cstdint>

// ---------------------------------------------------------------------------
// LeWinAttention round 13: R12 + GEMM CTA tile 128x128 (warp tile 32x64).
// ---------------------------------------------------------------------------

__device__ __half g_xh[134217728];    // x fp16          (256 MB)
__device__ __half g_qkvh[402653184];  // qkv fp16        (768 MB)
__device__ __half g_aouth[134217728]; // attn out fp16   (256 MB)
__device__ __half g_wh[262144];       // qkv_w + proj_w
__device__ __half g_biash[32768];     // bias [8][64][64] fp16

// ---------------- helpers --------------------------------------------------
__device__ __forceinline__ void mma_f16(float* d, const unsigned* a, const unsigned* b) {
    asm volatile(
        "mma.sync.aligned.m16n8k16.row.col.f32.f16.f16.f32 "
        "{%0,%1,%2,%3}, {%4,%5,%6,%7}, {%8,%9}, {%0,%1,%2,%3};"
        : "+f"(d[0]), "+f"(d[1]), "+f"(d[2]), "+f"(d[3])
        : "r"(a[0]), "r"(a[1]), "r"(a[2]), "r"(a[3]), "r"(b[0]), "r"(b[1]));
}
__device__ __forceinline__ void ldsm4(unsigned& r0, unsigned& r1, unsigned& r2,
                                      unsigned& r3, uint32_t addr) {
    asm volatile("ldmatrix.sync.aligned.m8n8.x4.shared.b16 {%0,%1,%2,%3}, [%4];"
                 : "=r"(r0), "=r"(r1), "=r"(r2), "=r"(r3) : "r"(addr));
}
__device__ __forceinline__ void ldsm4t(unsigned& r0, unsigned& r1, unsigned& r2,
                                       unsigned& r3, uint32_t addr) {
    asm volatile("ldmatrix.sync.aligned.m8n8.x4.trans.shared.b16 {%0,%1,%2,%3}, [%4];"
                 : "=r"(r0), "=r"(r1), "=r"(r2), "=r"(r3) : "r"(addr));
}
__device__ __forceinline__ void cpasync16(uint32_t dst, const void* src) {
    asm volatile("cp.async.cg.shared.global [%0], [%1], 16;" :: "r"(dst), "l"(src));
}
#define CP_COMMIT() asm volatile("cp.async.commit_group;" ::: "memory")
#define CP_WAIT2()  asm volatile("cp.async.wait_group 2;" ::: "memory")
#define CP_WAIT0()  asm volatile("cp.async.wait_group 0;" ::: "memory")

__device__ __forceinline__ void store2(float* p, float v0, float v1) {
    *(float2*)p = make_float2(v0, v1);
}
__device__ __forceinline__ void store2(__half* p, float v0, float v1) {
    *(__half2*)p = __floats2half2_rn(v0, v1);
}
__device__ __forceinline__ unsigned pack2(float x, float y) {
    __half2 h = __floats2half2_rn(x, y);
    return *(unsigned*)&h;
}

// FMA-pipe exp (no MUFU): exp(x) for x <= 0. rel err ~2e-6.
__device__ __forceinline__ float fexp(float x) {
    float y = fmaxf(x * 1.4426950408889634f, -126.0f);
    float r = y + 12582912.0f;
    float k = r - 12582912.0f;
    float f = y - k;
    float p = 0.0013333558f;
    p = fmaf(p, f, 0.0096181291f);
    p = fmaf(p, f, 0.0555041087f);
    p = fmaf(p, f, 0.2402264676f);
    p = fmaf(p, f, 0.6931471806f);
    p = fmaf(p, f, 1.0f);
    return __int_as_float(__float_as_int(p) + (((int)k) << 23));
}

// ---------------------------------------------------------------------------
__global__ void f2h_kernel(const float* __restrict__ in, __half* __restrict__ out, int n4)
{
    for (int i = blockIdx.x * blockDim.x + threadIdx.x; i < n4;
         i += gridDim.x * blockDim.x) {
        float4 v = *(const float4*)(in + (size_t)i * 4);
        __half2 h0 = __floats2half2_rn(v.x, v.y);
        __half2 h1 = __floats2half2_rn(v.z, v.w);
        uint2 u;
        u.x = *(unsigned*)&h0; u.y = *(unsigned*)&h1;
        *(uint2*)(out + (size_t)i * 4) = u;
    }
}

__global__ void bias_pre_kernel(const float* __restrict__ table,
                                const int* __restrict__ rpi,
                                __half* __restrict__ biash)
{
    int i = blockIdx.x * 256 + threadIdx.x;
    if (i < 4096) {
        int idx = rpi[i];
#pragma unroll
        for (int h = 0; h < 8; h++)
            biash[h * 4096 + i] = __float2half(table[idx * 8 + h]);
    }
}

// ---------------------------------------------------------------------------
// GEMM: CTA 128x128, warp tile 32x64 (4m x 2n warps), cp.async 4 stages.
// Stage: A[128][32h] 8KB + B[128][32h] 8KB = 16KB.
// swizzle: 16B chunk' = chunk ^ ((row>>1)&3).
// ---------------------------------------------------------------------------
#define GA_BYTES 8192
#define GSTAGE_B 16384
#define GNSTAGE  4

template <typename OutT>
__global__ void __launch_bounds__(256, 2)
gemm_cp_kernel(const __half* __restrict__ A, const __half* __restrict__ W,
               const float* __restrict__ bias, OutT* __restrict__ C, int Nc)
{
    extern __shared__ char sm[];
    uint32_t sbase;
    asm("{ .reg .u64 t; cvta.to.shared.u64 t, %1; cvt.u32.u64 %0, t; }"
        : "=r"(sbase) : "l"(sm));

    const int t    = threadIdx.x;
    const int lane = t & 31;
    const int gid  = lane >> 2;
    const int tig  = lane & 3;
    const int w    = t >> 5;
    const int wm   = w & 3;              // 4 warps in m
    const int wn   = w >> 2;             // 2 warps in n
    const size_t mBase = (size_t)blockIdx.y * 128;
    const int    nBase = blockIdx.x * 128;

    // cp.async: A 512 chunks + B 512 chunks; 2+2 per thread
    const int r0c = t >> 2;              // rows t>>2 and 64+(t>>2)
    const int cc  = t & 3;
    const int csw0 = (cc ^ ((r0c >> 1) & 3)) << 4;
    const __half* aS0 = A + (mBase + r0c) * 256 + cc * 8;
    const __half* aS1 = A + (mBase + 64 + r0c) * 256 + cc * 8;
    const __half* bS0 = W + ((size_t)nBase + r0c) * 256 + cc * 8;
    const __half* bS1 = W + ((size_t)nBase + 64 + r0c) * 256 + cc * 8;
    const uint32_t dA0 = sbase + r0c * 64 + csw0;
    const uint32_t dA1 = sbase + (64 + r0c) * 64 + csw0;
    const uint32_t dB0 = sbase + GA_BYTES + r0c * 64 + csw0;
    const uint32_t dB1 = sbase + GA_BYTES + (64 + r0c) * 64 + csw0;

    // ldmatrix addresses (stage 0; kk=1 is ^32)
    uint32_t aAddr[2], bAddr[4];
#pragma unroll
    for (int mt = 0; mt < 2; mt++) {
        int row = wm * 32 + mt * 16 + ((lane >> 3) & 1) * 8 + (lane & 7);
        aAddr[mt] = sbase + row * 64 + ((((lane >> 4) ^ ((row >> 1) & 3))) << 4);
    }
#pragma unroll
    for (int q = 0; q < 4; q++) {
        int n = wn * 64 + q * 16 + ((lane >> 4) << 3) + (lane & 7);
        bAddr[q] = sbase + GA_BYTES + n * 64
                 + ((((lane >> 3) & 1) ^ ((n >> 1) & 3)) << 4);
    }

    float acc[2][8][4];
#pragma unroll
    for (int mt = 0; mt < 2; mt++)
#pragma unroll
        for (int nt = 0; nt < 8; nt++)
#pragma unroll
            for (int i = 0; i < 4; i++) acc[mt][nt][i] = 0.f;

    auto issue = [&](int s) {
        const int k0 = s << 5;
        const uint32_t so = (s & 3) * GSTAGE_B;
        cpasync16(dA0 + so, aS0 + k0);
        cpasync16(dA1 + so, aS1 + k0);
        cpasync16(dB0 + so, bS0 + k0);
        cpasync16(dB1 + so, bS1 + k0);
    };

    issue(0); CP_COMMIT();
    issue(1); CP_COMMIT();
    issue(2); CP_COMMIT();

#pragma unroll
    for (int it = 0; it < 8; it++) {
        CP_WAIT2();
        __syncthreads();

        const uint32_t so = (it & 3) * GSTAGE_B;
#pragma unroll
        for (int kk = 0; kk < 2; kk++) {
            const uint32_t kx = kk << 5;
            unsigned af[2][4], bf[8][2];
#pragma unroll
            for (int mt = 0; mt < 2; mt++)
                ldsm4(af[mt][0], af[mt][1], af[mt][2], af[mt][3],
                      (aAddr[mt] + so) ^ kx);
#pragma unroll
            for (int q = 0; q < 4; q++)
                ldsm4(bf[2 * q][0], bf[2 * q][1], bf[2 * q + 1][0], bf[2 * q + 1][1],
                      (bAddr[q] + so) ^ kx);
#pragma unroll
            for (int mt = 0; mt < 2; mt++)
#pragma unroll
                for (int nt = 0; nt < 8; nt++)
                    mma_f16(acc[mt][nt], af[mt], bf[nt]);
        }

        if (it + 3 < 8) issue(it + 3);
        CP_COMMIT();
    }

    // ---- epilogue: + bias
#pragma unroll
    for (int mt = 0; mt < 2; mt++) {
#pragma unroll
        for (int nt = 0; nt < 8; nt++) {
            int col = nBase + wn * 64 + nt * 8 + (tig << 1);
            float b0 = bias[col], b1 = bias[col + 1];
            size_t r0 = mBase + wm * 32 + mt * 16 + gid;
            store2(C + r0 * Nc + col, acc[mt][nt][0] + b0, acc[mt][nt][1] + b1);
            store2(C + (r0 + 8) * Nc + col, acc[mt][nt][2] + b0, acc[mt][nt][3] + b1);
        }
    }
}

// ---------------------------------------------------------------------------
// Tensor-core attention (unchanged from R12): 1 CTA per window, warp = head.
// ---------------------------------------------------------------------------
__global__ void __launch_bounds__(256)
attn_mma_kernel(const __half* __restrict__ qkv, const __half* __restrict__ biash,
                __half* __restrict__ aout)
{
    extern __shared__ char sm[];
    uint32_t sbase;
    asm("{ .reg .u64 t; cvta.to.shared.u64 t, %1; cvt.u32.u64 %0, t; }"
        : "=r"(sbase) : "l"(sm));

    const int b    = blockIdx.x;
    const int t    = threadIdx.x;
    const int lane = t & 31;
    const int h    = t >> 5;
    const int gid  = lane >> 2;
    const int tig  = lane & 3;

    {
        const int r = t >> 2;
        const __half* src = qkv + ((size_t)b * 64 + r) * 768 + (t & 3) * 8;
        const uint32_t drow = sbase + r * 1536;
        const int rx = r & 7;
#pragma unroll
        for (int i = 0; i < 24; i++) {
            int cc = (t & 3) + (i << 2);
            cpasync16(drow + ((cc ^ rx) << 4), src + (i << 5));
        }
    }
    CP_COMMIT();
    CP_WAIT0();
    __syncthreads();

    uint32_t qA, kB, vB;
    {
        int r = ((lane >> 3) & 1) * 8 + (lane & 7);
        int ck = (h << 2) | (lane >> 4);
        qA = sbase + r * 1536 + ((ck ^ (r & 7)) << 4);
    }
    {
        int r = ((lane >> 4) << 3) + (lane & 7);
        int ck = ((8 + h) << 2) | ((lane >> 3) & 1);
        kB = sbase + r * 1536 + ((ck ^ (r & 7)) << 4);
    }
    {
        int tt = lane >> 3;
        int r = (tt & 1) * 8 + (lane & 7);
        int ck = ((16 + h) << 2) | (tt >> 1);
        vB = sbase + r * 1536 + ((ck ^ (r & 7)) << 4);
    }

    const float scale = 0.17677669529663687f;
    const __half* bia = biash + h * 4096;

#pragma unroll
    for (int h2 = 0; h2 < 2; h2++) {
        const int mt0 = h2 * 2;

        float sc[2][8][4];
#pragma unroll
        for (int mt = 0; mt < 2; mt++)
#pragma unroll
            for (int nt = 0; nt < 8; nt++)
#pragma unroll
                for (int i = 0; i < 4; i++) sc[mt][nt][i] = 0.f;

        unsigned kf[8][2][2];
#pragma unroll
        for (int ks = 0; ks < 2; ks++)
#pragma unroll
            for (int q = 0; q < 4; q++)
                ldsm4(kf[2 * q][ks][0], kf[2 * q][ks][1],
                      kf[2 * q + 1][ks][0], kf[2 * q + 1][ks][1],
                      (kB + q * 24576) ^ (ks << 5));
#pragma unroll
        for (int mt = 0; mt < 2; mt++)
#pragma unroll
            for (int ks = 0; ks < 2; ks++) {
                unsigned af[4];
                ldsm4(af[0], af[1], af[2], af[3],
                      (qA + (mt0 + mt) * 24576) ^ (ks << 5));
#pragma unroll
                for (int nt = 0; nt < 8; nt++)
                    mma_f16(sc[mt][nt], af, kf[nt][ks]);
            }

        float mx0[2], mx1[2];
#pragma unroll
        for (int mt = 0; mt < 2; mt++) {
            float m0 = -1e30f, m1 = -1e30f;
            int row = (mt0 + mt) * 16 + gid;
#pragma unroll
            for (int nt = 0; nt < 8; nt++) {
                float2 b0 = __half22float2(*(const __half2*)(bia + row * 64 + nt * 8 + 2 * tig));
                float2 b1 = __half22float2(*(const __half2*)(bia + (row + 8) * 64 + nt * 8 + 2 * tig));
                sc[mt][nt][0] = fmaf(sc[mt][nt][0], scale, b0.x);
                sc[mt][nt][1] = fmaf(sc[mt][nt][1], scale, b0.y);
                sc[mt][nt][2] = fmaf(sc[mt][nt][2], scale, b1.x);
                sc[mt][nt][3] = fmaf(sc[mt][nt][3], scale, b1.y);
                m0 = fmaxf(m0, fmaxf(sc[mt][nt][0], sc[mt][nt][1]));
                m1 = fmaxf(m1, fmaxf(sc[mt][nt][2], sc[mt][nt][3]));
            }
            m0 = fmaxf(m0, __shfl_xor_sync(0xffffffffu, m0, 1));
            m0 = fmaxf(m0, __shfl_xor_sync(0xffffffffu, m0, 2));
            m1 = fmaxf(m1, __shfl_xor_sync(0xffffffffu, m1, 1));
            m1 = fmaxf(m1, __shfl_xor_sync(0xffffffffu, m1, 2));
            mx0[mt] = m0; mx1[mt] = m1;
        }

        float s0[2], s1[2];
#pragma unroll
        for (int mt = 0; mt < 2; mt++) {
            float a0 = 0.f, a1 = 0.f;
#pragma unroll
            for (int nt = 0; nt < 8; nt++) {
                sc[mt][nt][0] = fexp(sc[mt][nt][0] - mx0[mt]); a0 += sc[mt][nt][0];
                sc[mt][nt][1] = fexp(sc[mt][nt][1] - mx0[mt]); a0 += sc[mt][nt][1];
                sc[mt][nt][2] = fexp(sc[mt][nt][2] - mx1[mt]); a1 += sc[mt][nt][2];
                sc[mt][nt][3] = fexp(sc[mt][nt][3] - mx1[mt]); a1 += sc[mt][nt][3];
            }
            a0 += __shfl_xor_sync(0xffffffffu, a0, 1);
            a0 += __shfl_xor_sync(0xffffffffu, a0, 2);
            a1 += __shfl_xor_sync(0xffffffffu, a1, 1);
            a1 += __shfl_xor_sync(0xffffffffu, a1, 2);
            s0[mt] = a0; s1[mt] = a1;
        }

        float pv[2][4][4];
#pragma unroll
        for (int mt = 0; mt < 2; mt++)
#pragma unroll
            for (int nt = 0; nt < 4; nt++)
#pragma unroll
                for (int i = 0; i < 4; i++) pv[mt][nt][i] = 0.f;

#pragma unroll
        for (int ks2 = 0; ks2 < 4; ks2++) {
            unsigned vb[4][2];
            uint32_t va = vB + ks2 * 24576;
            ldsm4t(vb[0][0], vb[0][1], vb[1][0], vb[1][1], va);
            ldsm4t(vb[2][0], vb[2][1], vb[3][0], vb[3][1], va ^ 32);
#pragma unroll
            for (int mt = 0; mt < 2; mt++) {
                unsigned pf[4];
                pf[0] = pack2(sc[mt][2 * ks2][0],     sc[mt][2 * ks2][1]);
                pf[1] = pack2(sc[mt][2 * ks2][2],     sc[mt][2 * ks2][3]);
                pf[2] = pack2(sc[mt][2 * ks2 + 1][0], sc[mt][2 * ks2 + 1][1]);
                pf[3] = pack2(sc[mt][2 * ks2 + 1][2], sc[mt][2 * ks2 + 1][3]);
#pragma unroll
                for (int nt = 0; nt < 4; nt++)
                    mma_f16(pv[mt][nt], pf, vb[nt]);
            }
        }

#pragma unroll
        for (int mt = 0; mt < 2; mt++) {
            float i0 = 1.f / s0[mt], i1 = 1.f / s1[mt];
            int row = (mt0 + mt) * 16 + gid;
            __half* o0 = aout + ((size_t)b * 64 + row) * 256 + h * 32 + 2 * tig;
            __half* o1 = o0 + 8 * 256;
#pragma unroll
            for (int nt = 0; nt < 4; nt++) {
                *(__half2*)(o0 + nt * 8) =
                    __floats2half2_rn(pv[mt][nt][0] * i0, pv[mt][nt][1] * i0);
                *(__half2*)(o1 + nt * 8) =
                    __floats2half2_rn(pv[mt][nt][2] * i1, pv[mt][nt][3] * i1);
            }
        }
    }
}

// ---------------------------------------------------------------------------
extern "C" void kernel_launch(void* const* d_in, const int* in_sizes, int n_in,
                              void* d_out, int out_size)
{
    const float* x   = (const float*)d_in[0];
    const float* qw  = (const float*)d_in[1];
    const float* qb  = (const float*)d_in[2];
    const float* pw  = (const float*)d_in[3];
    const float* pb  = (const float*)d_in[4];
    const float* tab = (const float*)d_in[5];
    const int*   rpi = (const int*)d_in[6];
    float* out = (float*)d_out;

    __half *xh = nullptr, *qkvh = nullptr, *aouth = nullptr, *wh = nullptr, *bh = nullptr;
    cudaGetSymbolAddress((void**)&xh,    g_xh);
    cudaGetSymbolAddress((void**)&qkvh,  g_qkvh);
    cudaGetSymbolAddress((void**)&aouth, g_aouth);
    cudaGetSymbolAddress((void**)&wh,    g_wh);
    cudaGetSymbolAddress((void**)&bh,    g_biash);

    const int smemBytes = GNSTAGE * GSTAGE_B;  // 65536 B
    cudaFuncSetAttribute(gemm_cp_kernel<__half>,
                         cudaFuncAttributeMaxDynamicSharedMemorySize, smemBytes);
    cudaFuncSetAttribute(gemm_cp_kernel<float>,
                         cudaFuncAttributeMaxDynamicSharedMemorySize, smemBytes);
    const int attnSmem = 98304;              // 96 KB
    cudaFuncSetAttribute(attn_mma_kernel,
                         cudaFuncAttributeMaxDynamicSharedMemorySize, attnSmem);

    // fp32 -> fp16 conversions + bias table
    f2h_kernel<<<32768, 256>>>(x, xh, 134217728 / 4);
    f2h_kernel<<<192, 256>>>(qw, wh, 196608 / 4);
    f2h_kernel<<<64, 256>>>(pw, wh + 196608, 65536 / 4);
    bias_pre_kernel<<<16, 256>>>(tab, rpi, bh);

    // QKV projection: [524288,256] @ [768,256]^T + b  -> fp16 qkv
    dim3 g1(768 / 128, (8192 * 64) / 128);   // (6, 4096)
    gemm_cp_kernel<__half><<<g1, 256, smemBytes>>>(xh, wh, qb, qkvh, 768);

    // Tensor-core windowed attention (fp16 io)
    attn_mma_kernel<<<8192, 256, attnSmem>>>(qkvh, bh, aouth);

    // Output projection: [524288,256] @ [256,256]^T + b -> fp32 out
    dim3 g3(256 / 128, (8192 * 64) / 128);   // (2, 4096)
    gemm_cp_kernel<float><<<g3, 256, smemBytes>>>(aouth, wh + 196608, pb, out, 256);
}